// round 8
// baseline (speedup 1.0000x reference)
#include <cuda_runtime.h>

#define NQ       10
#define DIM      1024
#define NLAYERS  4
#define NT       128          // 4 warps = TWO independent state-pairs (4 batch elems)
#define PI_F     3.14159265358979323846f

typedef unsigned long long u64;

// ---- packed f32x2 helpers (batchA in lo, batchB in hi) ----
__device__ __forceinline__ u64 pk2(float lo, float hi) {
    u64 r; asm("mov.b64 %0, {%1, %2};" : "=l"(r) : "f"(lo), "f"(hi)); return r;
}
__device__ __forceinline__ void upk2(u64 v, float& lo, float& hi) {
    asm("mov.b64 {%0, %1}, %2;" : "=f"(lo), "=f"(hi) : "l"(v));
}
__device__ __forceinline__ u64 fma2(u64 a, u64 b, u64 c) {
    u64 d; asm("fma.rn.f32x2 %0, %1, %2, %3;" : "=l"(d) : "l"(a), "l"(b), "l"(c)); return d;
}
__device__ __forceinline__ u64 mul2(u64 a, u64 b) {
    u64 d; asm("mul.rn.f32x2 %0, %1, %2;" : "=l"(d) : "l"(a), "l"(b)); return d;
}
__device__ __forceinline__ u64 add2(u64 a, u64 b) {
    u64 d; asm("add.rn.f32x2 %0, %1, %2;" : "=l"(d) : "l"(a), "l"(b)); return d;
}
__device__ __forceinline__ u64 neg2(u64 v) { return v ^ 0x8000000080000000ULL; }

// named barrier over one 64-thread half (warps {0,1} or {2,3})
__device__ __forceinline__ void barh(int h) {
    asm volatile("bar.sync %0, 64;" :: "r"(1 + h) : "memory");
}

// ---- scalar complex helpers (matrix construction only) ----
__device__ __forceinline__ float2 cmul(float2 a, float2 b) {
    return make_float2(fmaf(a.x, b.x, -a.y * b.y), fmaf(a.x, b.y, a.y * b.x));
}
__device__ __forceinline__ float2 cadd(float2 a, float2 b) { return make_float2(a.x + b.x, a.y + b.y); }
__device__ __forceinline__ float2 csub(float2 a, float2 b) { return make_float2(a.x - b.x, a.y - b.y); }
__device__ __forceinline__ float2 cscale(float s, float2 a) { return make_float2(s * a.x, s * a.y); }

// smem swizzle: phys(j) = j ^ s(j>>5), s(a) = (a&15) | ((a&8)<<1).
// Conflict-free for all three transpose patterns (verified per warp).
__device__ __forceinline__ int phys(int j) {
    int a = j >> 5;
    return j ^ ((a & 15) | ((a & 8) << 1));
}

// fused 2x2 gate on one amplitude pair, packed over 2 batch elements.
// c layout: [r00,i00,n00, r01,i01,n01, r10,i10,n10, r11,i11,n11] (n = -i)
__device__ __forceinline__ void gate2(const u64* __restrict__ c,
                                      u64& a0r, u64& a0i, u64& a1r, u64& a1i) {
    u64 b0r = fma2(c[0], a0r, fma2(c[2], a0i, fma2(c[3],  a1r, mul2(c[5],  a1i))));
    u64 b0i = fma2(c[0], a0i, fma2(c[1], a0r, fma2(c[3],  a1i, mul2(c[4],  a1r))));
    u64 b1r = fma2(c[6], a0r, fma2(c[8], a0i, fma2(c[9],  a1r, mul2(c[11], a1i))));
    u64 b1i = fma2(c[6], a0i, fma2(c[7], a0r, fma2(c[9],  a1i, mul2(c[10], a1r))));
    a0r = b0r; a0i = b0i; a1r = b1r; a1i = b1i;
}

// apply gate with coeffs C on register bit g (8 disjoint pairs among 16 regs)
#define APPLY_GATE(Cptr, g) do {                                            \
    u64 c_[12]; const u64* C_ = (Cptr);                                     \
    _Pragma("unroll") for (int q_ = 0; q_ < 12; ++q_) c_[q_] = C_[q_];      \
    const int bm_ = 1 << (g), lo_ = bm_ - 1;                                \
    _Pragma("unroll") for (int p_ = 0; p_ < 8; ++p_) {                      \
        const int i0_ = ((p_ & ~lo_) << 1) | (p_ & lo_);                    \
        const int i1_ = i0_ | bm_;                                          \
        gate2(c_, re[i0_], im[i0_], re[i1_], im[i1_]);                      \
    }                                                                       \
} while (0)

__global__ __launch_bounds__(NT)
void quantum_layer_kernel(const float* __restrict__ x,
                          const float* __restrict__ weight,
                          float* __restrict__ out)
{
    __shared__ float4 sv[2][DIM];            // 32 KB: per-half statevector
    __shared__ u64 wm[2][NLAYERS][NQ][12];   // fused gate coeffs, per half: 7.5 KB
    __shared__ unsigned short scat[DIM];     // CNOT-ring scatter LUT (shared): 2 KB
    __shared__ u64 wred[2][2][NQ];           // per-half cross-warp reduce

    const int tid = threadIdx.x;             // 0..127
    const int h   = tid >> 6;                // half: warps {0,1}->0, {2,3}->1
    const int t   = tid & 63;                // thread within half
    const int pairId = blockIdx.x * 2 + h;
    const int b0 = pairId * 2, b1 = b0 + 1;

    // ---- CNOT-ring: st'[j] = st[p(j)]. scat[p(j)] = phys(j). (all 128 threads)
    for (int j = tid; j < DIM; j += NT) {
        int src = j;
        src ^= (src & 1) << 9;                         // CNOT(9,0)
        #pragma unroll
        for (int q = 8; q >= 0; --q) {                 // CNOT(q,q+1)
            int cb = 9 - q, tb = 8 - q;
            src ^= ((src >> cb) & 1) << tb;
        }
        scat[src] = (unsigned short)phys(j);
    }

    // ---- fused per-wire matrices M = RZ(w2)*RY(w1)*RZ(w0)*RY(tanh(x)*pi)
    if (t < NQ) {
        const int w = t;
        float ang[2];
        ang[0] = tanhf(x[b0 * NQ + w]) * PI_F;
        ang[1] = tanhf(x[b1 * NQ + w]) * PI_F;
        for (int l = 0; l < NLAYERS; ++l) {
            float th1 = weight[(l * NQ + w) * 3 + 0];
            float th2 = weight[(l * NQ + w) * 3 + 1];
            float th3 = weight[(l * NQ + w) * 3 + 2];
            float2 m[2][4];
            #pragma unroll
            for (int bb = 0; bb < 2; ++bb) {
                float s0, c0, s1, c1, s2, c2, s3, c3;
                __sincosf(0.5f * ang[bb], &s0, &c0);
                __sincosf(0.5f * th1, &s1, &c1);
                __sincosf(0.5f * th2, &s2, &c2);
                __sincosf(0.5f * th3, &s3, &c3);
                float2 d1m = make_float2(c1, -s1), d1p = make_float2(c1, s1);
                float2 d3m = make_float2(c3, -s3), d3p = make_float2(c3, s3);
                m[bb][0] = cmul(d3m, csub(cscale(c2 * c0, d1m), cscale(s2 * s0, d1p)));
                m[bb][1] = cmul(d3m, csub(cscale(-c2 * s0, d1m), cscale(s2 * c0, d1p)));
                m[bb][2] = cmul(d3p, cadd(cscale(s2 * c0, d1m), cscale(c2 * s0, d1p)));
                m[bb][3] = cmul(d3p, csub(cscale(c2 * c0, d1p), cscale(s2 * s0, d1m)));
            }
            u64* dst = wm[h][l][w];
            #pragma unroll
            for (int e = 0; e < 4; ++e) {
                dst[e * 3 + 0] = pk2(m[0][e].x,  m[1][e].x);   // re
                dst[e * 3 + 1] = pk2(m[0][e].y,  m[1][e].y);   // im
                dst[e * 3 + 2] = pk2(-m[0][e].y, -m[1][e].y);  // -im
            }
        }
    }
    __syncthreads();   // scat + both halves' wm ready; after this, halves are independent

    // ---- state: 16 amps/thread, three arrangements per layer:
    //  A: j = (t<<4)|r                 gates on bits 0..3 (wires 9..6)
    //  B: j = (t>>4)<<8|(r<<4)|(t&15)  gates on bits 4..7 (wires 5..2)
    //  C: j = (r<<6)|t                 gates on bits 8,9 (reg bits 2,3; wires 1,0)
    u64 re[16], im[16];

    const int tbhi = (t >> 4) << 8, tblo = t & 15;

    for (int l = 0; l < NLAYERS; ++l) {
        if (l == 0) {
            // |0..0>: A-group result is a gate-column product on thread 0 only
            #pragma unroll
            for (int i = 0; i < 16; ++i) { re[i] = 0ULL; im[i] = 0ULL; }
            if (t == 0) {
                #pragma unroll
                for (int r = 0; r < 16; ++r) {
                    u64 ar = pk2(1.0f, 1.0f), ai = 0ULL;
                    #pragma unroll
                    for (int g = 0; g < 4; ++g) {
                        const u64* C = wm[h][0][9 - g];
                        const int sel = (r >> g) & 1;
                        u64 br = C[6 * sel], bi = C[6 * sel + 1];
                        u64 nr = fma2(ar, br, neg2(mul2(ai, bi)));
                        u64 ni = fma2(ar, bi, mul2(ai, br));
                        ar = nr; ai = ni;
                    }
                    re[r] = ar; im[r] = ai;
                }
            }
        } else {
            // load A (own slots — written by scat store of previous layer)
            #pragma unroll
            for (int r = 0; r < 16; ++r) {
                float4 v = sv[h][phys((t << 4) | r)];
                re[r] = pk2(v.x, v.y); im[r] = pk2(v.z, v.w);
            }
            APPLY_GATE(wm[h][l][9], 0);
            APPLY_GATE(wm[h][l][8], 1);
            APPLY_GATE(wm[h][l][7], 2);
            APPLY_GATE(wm[h][l][6], 3);
        }
        // store A (same per-thread slots as the A load: no hazard)
        #pragma unroll
        for (int r = 0; r < 16; ++r) {
            float4 v; upk2(re[r], v.x, v.y); upk2(im[r], v.z, v.w);
            sv[h][phys((t << 4) | r)] = v;
        }
        barh(h);

        // ---- group B
        #pragma unroll
        for (int r = 0; r < 16; ++r) {
            float4 v = sv[h][phys(tbhi | (r << 4) | tblo)];
            re[r] = pk2(v.x, v.y); im[r] = pk2(v.z, v.w);
        }
        APPLY_GATE(wm[h][l][5], 0);
        APPLY_GATE(wm[h][l][4], 1);
        APPLY_GATE(wm[h][l][3], 2);
        APPLY_GATE(wm[h][l][2], 3);
        #pragma unroll
        for (int r = 0; r < 16; ++r) {
            float4 v; upk2(re[r], v.x, v.y); upk2(im[r], v.z, v.w);
            sv[h][phys(tbhi | (r << 4) | tblo)] = v;
        }
        barh(h);

        // ---- group C
        #pragma unroll
        for (int r = 0; r < 16; ++r) {
            float4 v = sv[h][phys((r << 6) | t)];
            re[r] = pk2(v.x, v.y); im[r] = pk2(v.z, v.w);
        }
        APPLY_GATE(wm[h][l][1], 2);
        APPLY_GATE(wm[h][l][0], 3);
        if (l < NLAYERS - 1) {
            barh(h);   // all C loads done before permuted scatter
            #pragma unroll
            for (int r = 0; r < 16; ++r) {
                float4 v; upk2(re[r], v.x, v.y); upk2(im[r], v.z, v.w);
                sv[h][scat[(r << 6) | t]] = v;
            }
            barh(h);
        }
    }

    // ---- measurement in arrangement C: amp x = (r<<6)|t.
    // Final CNOT ring folded into signs: bit k of pinv(x) = parity(x & mask_k),
    // mask_k = bits k..9 (k=0..8), mask_9 = 0x1FF.
    #pragma unroll
    for (int i = 0; i < 16; ++i)
        re[i] = fma2(re[i], re[i], mul2(im[i], im[i]));   // packed |amp|^2

    const u64 pone = pk2(1.0f, 1.0f), none = pk2(-1.0f, -1.0f);
    const int warp = (t >> 5) & 1;           // warp within half
    const unsigned fullmask = 0xffffffffu;
    #pragma unroll
    for (int w = 0; w < NQ; ++w) {
        const int k = 9 - w;
        const unsigned mask = (k == 9) ? 0x1FFu : (0x3FFu & ~((1u << k) - 1u));
        const unsigned mr = (mask >> 6) & 15u, mt = mask & 63u;
        u64 acc = 0ULL;
        #pragma unroll
        for (int r = 0; r < 16; ++r)
            acc = fma2(re[r], (__popc((unsigned)r & mr) & 1) ? none : pone, acc);
        if (__popc((unsigned)t & mt) & 1) acc = neg2(acc);
        #pragma unroll
        for (int off = 16; off; off >>= 1) {
            u64 o = __shfl_xor_sync(fullmask, acc, off);
            acc = add2(acc, o);
        }
        if ((t & 31) == 0) wred[h][warp][w] = acc;
    }
    barh(h);
    if (t < NQ) {
        u64 s = add2(wred[h][0][t], wred[h][1][t]);
        float ra, rb; upk2(s, ra, rb);
        out[b0 * NQ + t] = ra;
        out[b1 * NQ + t] = rb;
    }
}

extern "C" void kernel_launch(void* const* d_in, const int* in_sizes, int n_in,
                              void* d_out, int out_size) {
    const float* x      = (const float*)d_in[0];   // (16384, 10) float32
    const float* weight = (const float*)d_in[1];   // (4, 10, 3)  float32
    float* out          = (float*)d_out;           // (16384, 10) float32
    const int batch  = in_sizes[0] / NQ;
    const int blocks = batch / 4;                  // 4 batch elems per block
    quantum_layer_kernel<<<blocks, NT>>>(x, weight, out);
}

// round 9
// speedup vs baseline: 1.1036x; 1.1036x over previous
#include <cuda_runtime.h>

#define NQ       10
#define DIM      1024
#define NLAYERS  4
#define NT       64           // 64 threads = 2 warps = one state-pair (2 batch elems)
#define PI_F     3.14159265358979323846f

typedef unsigned long long u64;

// ---- packed f32x2 helpers (batch0 in lo, batch1 in hi) ----
__device__ __forceinline__ u64 pk2(float lo, float hi) {
    u64 r; asm("mov.b64 %0, {%1, %2};" : "=l"(r) : "f"(lo), "f"(hi)); return r;
}
__device__ __forceinline__ void upk2(u64 v, float& lo, float& hi) {
    asm("mov.b64 {%0, %1}, %2;" : "=f"(lo), "=f"(hi) : "l"(v));
}
__device__ __forceinline__ u64 fma2(u64 a, u64 b, u64 c) {
    u64 d; asm("fma.rn.f32x2 %0, %1, %2, %3;" : "=l"(d) : "l"(a), "l"(b), "l"(c)); return d;
}
__device__ __forceinline__ u64 mul2(u64 a, u64 b) {
    u64 d; asm("mul.rn.f32x2 %0, %1, %2;" : "=l"(d) : "l"(a), "l"(b)); return d;
}
__device__ __forceinline__ u64 add2(u64 a, u64 b) {
    u64 d; asm("add.rn.f32x2 %0, %1, %2;" : "=l"(d) : "l"(a), "l"(b)); return d;
}
__device__ __forceinline__ u64 neg2(u64 v) { return v ^ 0x8000000080000000ULL; }

// packed complex multiply: (zr,zi) = (ar,ai)*(br,bi)
__device__ __forceinline__ void cmul2(u64 ar, u64 ai, u64 br, u64 bi, u64& zr, u64& zi) {
    zr = fma2(ar, br, neg2(mul2(ai, bi)));
    zi = fma2(ar, bi, mul2(ai, br));
}

// ---- scalar complex helpers (matrix construction only) ----
__device__ __forceinline__ float2 cmul(float2 a, float2 b) {
    return make_float2(fmaf(a.x, b.x, -a.y * b.y), fmaf(a.x, b.y, a.y * b.x));
}
__device__ __forceinline__ float2 cadd(float2 a, float2 b) { return make_float2(a.x + b.x, a.y + b.y); }
__device__ __forceinline__ float2 csub(float2 a, float2 b) { return make_float2(a.x - b.x, a.y - b.y); }
__device__ __forceinline__ float2 cscale(float s, float2 a) { return make_float2(s * a.x, s * a.y); }

// smem swizzle: phys(j) = j ^ s(j>>5), s(a) = (a&15) | ((a&8)<<1).
__device__ __forceinline__ int phys(int j) {
    int a = j >> 5;
    return j ^ ((a & 15) | ((a & 8) << 1));
}

// real RY rotation on register bit g: 8 disjoint pairs, 8 packed ops/pair
#define APPLY_RY(CC, SS, g) do {                                            \
    const u64 c_ = (CC), s_ = (SS), ns_ = neg2(s_);                         \
    const int bm_ = 1 << (g), lo_ = bm_ - 1;                                \
    _Pragma("unroll") for (int p_ = 0; p_ < 8; ++p_) {                      \
        const int i0_ = ((p_ & ~lo_) << 1) | (p_ & lo_);                    \
        const int i1_ = i0_ | bm_;                                          \
        u64 b0r = fma2(c_, re[i0_], mul2(ns_, re[i1_]));                    \
        u64 b0i = fma2(c_, im[i0_], mul2(ns_, im[i1_]));                    \
        u64 b1r = fma2(c_, re[i1_], mul2(s_,  re[i0_]));                    \
        u64 b1i = fma2(c_, im[i1_], mul2(s_,  im[i0_]));                    \
        re[i0_] = b0r; im[i0_] = b0i; re[i1_] = b1r; im[i1_] = b1i;         \
    }                                                                       \
} while (0)

__global__ __launch_bounds__(NT)
void quantum_layer_kernel(const float* __restrict__ x,
                          const float* __restrict__ weight,
                          float* __restrict__ out)
{
    __shared__ float4 sv[DIM];               // 16 KB statevector
    __shared__ u64 ryc[NLAYERS][NQ], rys[NLAYERS][NQ];   // RY(delta) coeffs
    __shared__ u64 Zg[NLAYERS][NQ][2], Ze[NLAYERS][NQ][2]; // e^{i*gamma}, e^{i*eps} per wire
    __shared__ u64 ghs[NLAYERS][NQ], ehs[NLAYERS][NQ];   // half-angles (packed floats)
    __shared__ u64 Cg[NLAYERS][2], Ce[NLAYERS][2];       // e^{-i*sum(gamma/2)}, e^{-i*sum(eps/2)}
    __shared__ unsigned short scat[DIM];     // CNOT-ring scatter LUT (swizzled)
    __shared__ u64 wred[2][NQ];              // cross-warp measurement reduce

    const int t  = threadIdx.x;              // 0..63
    const int b0 = blockIdx.x * 2, b1 = b0 + 1;

    // ---- CNOT-ring: st'[j] = st[p(j)]. scat[p(j)] = phys(j).
    for (int j = t; j < DIM; j += NT) {
        int src = j;
        src ^= (src & 1) << 9;                         // CNOT(9,0)
        #pragma unroll
        for (int q = 8; q >= 0; --q) {                 // CNOT(q,q+1)
            int cb = 9 - q, tb = 8 - q;
            src ^= ((src >> cb) & 1) << tb;
        }
        scat[src] = (unsigned short)phys(j);
    }

    // ---- per-wire fused matrix -> ZYZ: M = RZ(gamma) RY(delta) RZ(eps)
    if (t < NQ) {
        const int w = t;
        float ang[2];
        ang[0] = tanhf(x[b0 * NQ + w]) * PI_F;
        ang[1] = tanhf(x[b1 * NQ + w]) * PI_F;
        for (int l = 0; l < NLAYERS; ++l) {
            float th1 = weight[(l * NQ + w) * 3 + 0];
            float th2 = weight[(l * NQ + w) * 3 + 1];
            float th3 = weight[(l * NQ + w) * 3 + 2];
            float cc[2], ss[2], gh[2], eh[2], zgr[2], zgi[2], zer[2], zei[2];
            #pragma unroll
            for (int bb = 0; bb < 2; ++bb) {
                float s0, c0, s1, c1, s2, c2, s3, c3;
                __sincosf(0.5f * ang[bb], &s0, &c0);
                __sincosf(0.5f * th1, &s1, &c1);
                __sincosf(0.5f * th2, &s2, &c2);
                __sincosf(0.5f * th3, &s3, &c3);
                float2 d1m = make_float2(c1, -s1), d1p = make_float2(c1, s1);
                float2 d3m = make_float2(c3, -s3), d3p = make_float2(c3, s3);
                // u = m00, v = m10 of the fused SU(2) matrix
                float2 u = cmul(d3m, csub(cscale(c2 * c0, d1m), cscale(s2 * s0, d1p)));
                float2 v = cmul(d3p, cadd(cscale(s2 * c0, d1m), cscale(c2 * s0, d1p)));
                float c = sqrtf(fmaf(u.x, u.x, u.y * u.y));
                float s = sqrtf(fmaf(v.x, v.x, v.y * v.y));
                float au = atan2f(u.y, u.x);
                float av = atan2f(v.y, v.x);
                cc[bb] = c; ss[bb] = s;
                gh[bb] = 0.5f * (av - au);      // gamma/2
                eh[bb] = 0.5f * (-av - au);     // eps/2
                float sg, cg, se, ce;
                __sincosf(2.0f * gh[bb], &sg, &cg);   // e^{i*gamma}
                __sincosf(2.0f * eh[bb], &se, &ce);   // e^{i*eps}
                zgr[bb] = cg; zgi[bb] = sg; zer[bb] = ce; zei[bb] = se;
            }
            ryc[l][w] = pk2(cc[0], cc[1]);
            rys[l][w] = pk2(ss[0], ss[1]);
            ghs[l][w] = pk2(gh[0], gh[1]);
            ehs[l][w] = pk2(eh[0], eh[1]);
            Zg[l][w][0] = pk2(zgr[0], zgr[1]); Zg[l][w][1] = pk2(zgi[0], zgi[1]);
            Ze[l][w][0] = pk2(zer[0], zer[1]); Ze[l][w][1] = pk2(zei[0], zei[1]);
        }
    }
    __syncthreads();
    // per-layer constants C = e^{-i*sum(half-angles)}
    if (t < NLAYERS * 2) {
        const int l = t >> 1, which = t & 1;            // 0: gamma, 1: eps
        u64 s = 0ULL;
        #pragma unroll
        for (int w = 0; w < NQ; ++w) s = add2(s, which ? ehs[l][w] : ghs[l][w]);
        float a0, a1; upk2(s, a0, a1);
        float s0, c0, s1, c1;
        __sincosf(-a0, &s0, &c0);
        __sincosf(-a1, &s1, &c1);
        if (which) { Ce[l][0] = pk2(c0, c1); Ce[l][1] = pk2(s0, s1); }
        else       { Cg[l][0] = pk2(c0, c1); Cg[l][1] = pk2(s0, s1); }
    }
    __syncthreads();

    // ---- state: 16 amps/thread, three arrangements per layer:
    //  A: j = (t<<4)|r                 bits 0..3 = r (wires 9..6), bits 4..9 = t (wires 5..0)
    //  B: j = (t>>4)<<8|(r<<4)|(t&15)  gates on bits 4..7 (wires 5..2)
    //  C: j = (r<<6)|t                 bits 0..5 = t (wires 9..4), bits 6..9 = r (wires 3..0)
    u64 re[16], im[16];

    const int tbhi = (t >> 4) << 8, tblo = t & 15;

    for (int l = 0; l < NLAYERS; ++l) {
        if (l == 0) {
            // |0..0>: D_eps(0) is a global phase (dropped). A-group RYs from basis
            // state: real column product on thread 0 only.
            #pragma unroll
            for (int i = 0; i < 16; ++i) { re[i] = 0ULL; im[i] = 0ULL; }
            if (t == 0) {
                #pragma unroll
                for (int r = 0; r < 16; ++r) {
                    u64 v = pk2(1.0f, 1.0f);
                    #pragma unroll
                    for (int g = 0; g < 4; ++g)
                        v = mul2(v, ((r >> g) & 1) ? rys[0][9 - g] : ryc[0][9 - g]);
                    re[r] = v;
                }
            }
        } else {
            // load A, then apply D_eps(l) (rightmost factor of layer l)
            #pragma unroll
            for (int r = 0; r < 16; ++r) {
                float4 v = sv[phys((t << 4) | r)];
                re[r] = pk2(v.x, v.y); im[r] = pk2(v.z, v.w);
            }
            // zt: thread-bit part (bits 4..9 -> wires 5..0), times C_eps
            u64 ztr = Ce[l][0], zti = Ce[l][1];
            #pragma unroll
            for (int k = 0; k < 6; ++k)
                if ((t >> k) & 1) {
                    u64 nr, ni;
                    cmul2(ztr, zti, Ze[l][5 - k][0], Ze[l][5 - k][1], nr, ni);
                    ztr = nr; zti = ni;
                }
            // doubling table over r bits 0..3 (wire 9-b for bit b)
            u64 wr[16], wi[16];
            wr[0] = ztr; wi[0] = zti;
            #pragma unroll
            for (int b = 0; b < 4; ++b) {
                const u64 fr = Ze[l][9 - b][0], fi = Ze[l][9 - b][1];
                #pragma unroll
                for (int idx = 0; idx < 8; ++idx) {
                    if (idx < (1 << b))
                        cmul2(wr[idx], wi[idx], fr, fi, wr[idx | (1 << b)], wi[idx | (1 << b)]);
                }
            }
            #pragma unroll
            for (int r = 0; r < 16; ++r) {
                u64 nr, ni;
                cmul2(re[r], im[r], wr[r], wi[r], nr, ni);
                re[r] = nr; im[r] = ni;
            }
            // A-group RYs: wires 9..6 on reg bits 0..3
            APPLY_RY(ryc[l][9], rys[l][9], 0);
            APPLY_RY(ryc[l][8], rys[l][8], 1);
            APPLY_RY(ryc[l][7], rys[l][7], 2);
            APPLY_RY(ryc[l][6], rys[l][6], 3);
        }
        #pragma unroll
        for (int r = 0; r < 16; ++r) {
            float4 v; upk2(re[r], v.x, v.y); upk2(im[r], v.z, v.w);
            sv[phys((t << 4) | r)] = v;
        }
        __syncthreads();

        // ---- group B: wires 5..2 on reg bits 0..3
        #pragma unroll
        for (int r = 0; r < 16; ++r) {
            float4 v = sv[phys(tbhi | (r << 4) | tblo)];
            re[r] = pk2(v.x, v.y); im[r] = pk2(v.z, v.w);
        }
        APPLY_RY(ryc[l][5], rys[l][5], 0);
        APPLY_RY(ryc[l][4], rys[l][4], 1);
        APPLY_RY(ryc[l][3], rys[l][3], 2);
        APPLY_RY(ryc[l][2], rys[l][2], 3);
        #pragma unroll
        for (int r = 0; r < 16; ++r) {
            float4 v; upk2(re[r], v.x, v.y); upk2(im[r], v.z, v.w);
            sv[phys(tbhi | (r << 4) | tblo)] = v;
        }
        __syncthreads();

        // ---- group C: wires 1,0 on reg bits 2,3
        #pragma unroll
        for (int r = 0; r < 16; ++r) {
            float4 v = sv[phys((r << 6) | t)];
            re[r] = pk2(v.x, v.y); im[r] = pk2(v.z, v.w);
        }
        APPLY_RY(ryc[l][1], rys[l][1], 2);
        APPLY_RY(ryc[l][0], rys[l][0], 3);

        if (l < NLAYERS - 1) {
            // apply D_gamma(l) (leftmost factor; l=3's is dropped: |.|^2 invariant)
            // C arrangement: bits 0..5 = t -> wires 9..4; bits 6..9 = r -> wires 3..0
            u64 ztr = Cg[l][0], zti = Cg[l][1];
            #pragma unroll
            for (int k = 0; k < 6; ++k)
                if ((t >> k) & 1) {
                    u64 nr, ni;
                    cmul2(ztr, zti, Zg[l][9 - k][0], Zg[l][9 - k][1], nr, ni);
                    ztr = nr; zti = ni;
                }
            u64 wr[16], wi[16];
            wr[0] = ztr; wi[0] = zti;
            #pragma unroll
            for (int b = 0; b < 4; ++b) {
                const u64 fr = Zg[l][3 - b][0], fi = Zg[l][3 - b][1];
                #pragma unroll
                for (int idx = 0; idx < 8; ++idx) {
                    if (idx < (1 << b))
                        cmul2(wr[idx], wi[idx], fr, fi, wr[idx | (1 << b)], wi[idx | (1 << b)]);
                }
            }
            #pragma unroll
            for (int r = 0; r < 16; ++r) {
                u64 nr, ni;
                cmul2(re[r], im[r], wr[r], wi[r], nr, ni);
                re[r] = nr; im[r] = ni;
            }
            __syncthreads();   // all C loads done before permuted scatter
            #pragma unroll
            for (int r = 0; r < 16; ++r) {
                float4 v; upk2(re[r], v.x, v.y); upk2(im[r], v.z, v.w);
                sv[scat[(r << 6) | t]] = v;
            }
            __syncthreads();
        }
    }

    // ---- measurement in arrangement C: amp x = (r<<6)|t.
    // Final CNOT ring folded into signs: bit k of pinv(x) = parity(x & mask_k),
    // mask_k = bits k..9 (k=0..8), mask_9 = 0x1FF.
    #pragma unroll
    for (int i = 0; i < 16; ++i)
        re[i] = fma2(re[i], re[i], mul2(im[i], im[i]));   // packed |amp|^2

    const u64 pone = pk2(1.0f, 1.0f), none = pk2(-1.0f, -1.0f);
    const int warp = t >> 5;
    const unsigned fullmask = 0xffffffffu;
    #pragma unroll
    for (int w = 0; w < NQ; ++w) {
        const int k = 9 - w;
        const unsigned mask = (k == 9) ? 0x1FFu : (0x3FFu & ~((1u << k) - 1u));
        const unsigned mr = (mask >> 6) & 15u, mt = mask & 63u;
        u64 acc = 0ULL;
        #pragma unroll
        for (int r = 0; r < 16; ++r)
            acc = fma2(re[r], (__popc((unsigned)r & mr) & 1) ? none : pone, acc);
        if (__popc((unsigned)t & mt) & 1) acc = neg2(acc);
        #pragma unroll
        for (int off = 16; off; off >>= 1) {
            u64 o = __shfl_xor_sync(fullmask, acc, off);
            acc = add2(acc, o);
        }
        if ((t & 31) == 0) wred[warp][w] = acc;
    }
    __syncthreads();
    if (t < NQ) {
        u64 s = add2(wred[0][t], wred[1][t]);
        float ra, rb; upk2(s, ra, rb);
        out[b0 * NQ + t] = ra;
        out[b1 * NQ + t] = rb;
    }
}

extern "C" void kernel_launch(void* const* d_in, const int* in_sizes, int n_in,
                              void* d_out, int out_size) {
    const float* x      = (const float*)d_in[0];   // (16384, 10) float32
    const float* weight = (const float*)d_in[1];   // (4, 10, 3)  float32
    float* out          = (float*)d_out;           // (16384, 10) float32
    const int batch  = in_sizes[0] / NQ;
    const int blocks = batch / 2;                  // 2 batch elems per block
    quantum_layer_kernel<<<blocks, NT>>>(x, weight, out);
}